// round 7
// baseline (speedup 1.0000x reference)
#include <cuda_runtime.h>
#include <math_constants.h>
#include <cstddef>
#include <cstdint>

// Problem constants
#define Bb 2
#define Qq 2048
#define Kk 2048
#define DMm 512
#define Hh 8
#define Ff 5
#define DHh 64
#define TK 64

// Bias lookup table
#define NT 2048
#define DMAXV 14.15f   // > sqrt(200) = max possible distance for locs in [0,10]^2

// Scratch (alloc-free rule: __device__ globals)
__device__ float g_q[Bb * Qq * DMm];
__device__ float g_k[Bb * Kk * DMm];
__device__ float g_v[Bb * Kk * DMm];
__device__ float g_ctx[Bb * Qq * DMm];
__device__ float g_btab[Hh * NT];

// ---------------------------------------------------------------------------
// Build per-head bias table
// ---------------------------------------------------------------------------
__global__ void build_bias_table(const float* __restrict__ apar,
                                 const float* __restrict__ bpar,
                                 const float* __restrict__ cpar)
{
    const int h = blockIdx.x;
    float af[Ff], bf[Ff], cf[Ff];
#pragma unroll
    for (int f = 0; f < Ff; ++f) {
        af[f] = apar[h * Ff + f];
        bf[f] = fabsf(bpar[h * Ff + f]);
        cf[f] = cpar[h * Ff + f];
    }
    const float step = DMAXV / (float)(NT - 1);
    for (int i = threadIdx.x; i < NT; i += blockDim.x) {
        float d = i * step;
        float s = 0.f;
#pragma unroll
        for (int f = 0; f < Ff; ++f) {
            float t = d - cf[f];
            s = fmaf(af[f], __expf(-bf[f] * t * t), s);
        }
        g_btab[h * NT + i] = s;
    }
}

// ---------------------------------------------------------------------------
// tf32 tensor-core GEMM with hi/lo split for fp32-class accuracy.
// C[M,512] = (A[M,512] @ W[512,512] + bias) * scale
// Block tile 64x64, 128 threads (4 warps in 2x2), warp tile 32x32,
// mma.sync.m16n8k8.tf32, K-slab 16.
// ---------------------------------------------------------------------------
__device__ __forceinline__ float tf32_rna(float x) {
    uint32_t u;
    asm("cvt.rna.tf32.f32 %0, %1;" : "=r"(u) : "f"(x));
    return __uint_as_float(u);
}

__device__ __forceinline__ void mma_tf32(float* c,
    uint32_t a0, uint32_t a1, uint32_t a2, uint32_t a3,
    uint32_t b0, uint32_t b1)
{
    asm volatile(
        "mma.sync.aligned.m16n8k8.row.col.f32.tf32.tf32.f32 "
        "{%0,%1,%2,%3}, {%4,%5,%6,%7}, {%8,%9}, {%0,%1,%2,%3};"
        : "+f"(c[0]), "+f"(c[1]), "+f"(c[2]), "+f"(c[3])
        : "r"(a0), "r"(a1), "r"(a2), "r"(a3), "r"(b0), "r"(b1));
}

__device__ __forceinline__ void gemm512_tc_body(
    const float* __restrict__ A, const float* __restrict__ W,
    const float* __restrict__ bias, float* __restrict__ C, float scale,
    int rowBase, int colBase)
{
    __shared__ __align__(16) float Ah[64][20], Al[64][20];   // pad 20: conflict-free frags
    __shared__ __align__(16) float Bh[16][72], Bl[16][72];   // pad 72: conflict-free frags

    const int tid = threadIdx.x;          // 128
    const int lane = tid & 31;
    const int warp = tid >> 5;            // 0..3
    const int wm = (warp & 1) * 32;
    const int wn = (warp >> 1) * 32;
    const int g = lane >> 2;              // 0..7
    const int t = lane & 3;               // 0..3

    float acc[2][4][4];
#pragma unroll
    for (int mi = 0; mi < 2; ++mi)
#pragma unroll
        for (int ni = 0; ni < 4; ++ni)
#pragma unroll
            for (int e = 0; e < 4; ++e) acc[mi][ni][e] = 0.f;

    // Global->shared index plan (256 float4 per array per slab, 2 per thread)
    const int arow = tid >> 2;            // 0..31 (+32 second pass)
    const int acol = (tid & 3) << 2;      // 0,4,8,12
    const int brow = tid >> 4;            // 0..7  (+8 second pass)
    const int bcol = (tid & 15) << 2;     // 0..60

    for (int k0 = 0; k0 < 512; k0 += 16) {
        __syncthreads();
#pragma unroll
        for (int p = 0; p < 2; ++p) {
            float4 va = *reinterpret_cast<const float4*>(
                A + (size_t)(rowBase + arow + p * 32) * 512 + k0 + acol);
            float4 hA, lA;
            hA.x = tf32_rna(va.x); lA.x = tf32_rna(va.x - hA.x);
            hA.y = tf32_rna(va.y); lA.y = tf32_rna(va.y - hA.y);
            hA.z = tf32_rna(va.z); lA.z = tf32_rna(va.z - hA.z);
            hA.w = tf32_rna(va.w); lA.w = tf32_rna(va.w - hA.w);
            *reinterpret_cast<float4*>(&Ah[arow + p * 32][acol]) = hA;
            *reinterpret_cast<float4*>(&Al[arow + p * 32][acol]) = lA;

            float4 vb = *reinterpret_cast<const float4*>(
                W + (size_t)(k0 + brow + p * 8) * 512 + colBase + bcol);
            float4 hB, lB;
            hB.x = tf32_rna(vb.x); lB.x = tf32_rna(vb.x - hB.x);
            hB.y = tf32_rna(vb.y); lB.y = tf32_rna(vb.y - hB.y);
            hB.z = tf32_rna(vb.z); lB.z = tf32_rna(vb.z - hB.z);
            hB.w = tf32_rna(vb.w); lB.w = tf32_rna(vb.w - hB.w);
            *reinterpret_cast<float4*>(&Bh[brow + p * 8][bcol]) = hB;
            *reinterpret_cast<float4*>(&Bl[brow + p * 8][bcol]) = lB;
        }
        __syncthreads();

#pragma unroll
        for (int kk = 0; kk < 16; kk += 8) {
            uint32_t ah[2][4], al[2][4];
#pragma unroll
            for (int mi = 0; mi < 2; ++mi) {
                int r0 = wm + mi * 16 + g;
                ah[mi][0] = __float_as_uint(Ah[r0][kk + t]);
                ah[mi][1] = __float_as_uint(Ah[r0 + 8][kk + t]);
                ah[mi][2] = __float_as_uint(Ah[r0][kk + t + 4]);
                ah[mi][3] = __float_as_uint(Ah[r0 + 8][kk + t + 4]);
                al[mi][0] = __float_as_uint(Al[r0][kk + t]);
                al[mi][1] = __float_as_uint(Al[r0 + 8][kk + t]);
                al[mi][2] = __float_as_uint(Al[r0][kk + t + 4]);
                al[mi][3] = __float_as_uint(Al[r0 + 8][kk + t + 4]);
            }
            uint32_t bh[4][2], bl[4][2];
#pragma unroll
            for (int ni = 0; ni < 4; ++ni) {
                int c0 = wn + ni * 8 + g;
                bh[ni][0] = __float_as_uint(Bh[kk + t][c0]);
                bh[ni][1] = __float_as_uint(Bh[kk + t + 4][c0]);
                bl[ni][0] = __float_as_uint(Bl[kk + t][c0]);
                bl[ni][1] = __float_as_uint(Bl[kk + t + 4][c0]);
            }
#pragma unroll
            for (int mi = 0; mi < 2; ++mi)
#pragma unroll
                for (int ni = 0; ni < 4; ++ni) {
                    mma_tf32(acc[mi][ni], ah[mi][0], ah[mi][1], ah[mi][2], ah[mi][3],
                             bh[ni][0], bh[ni][1]);
                    mma_tf32(acc[mi][ni], ah[mi][0], ah[mi][1], ah[mi][2], ah[mi][3],
                             bl[ni][0], bl[ni][1]);
                    mma_tf32(acc[mi][ni], al[mi][0], al[mi][1], al[mi][2], al[mi][3],
                             bh[ni][0], bh[ni][1]);
                }
        }
    }

    // Epilogue: c0,c1 -> (row, 2t), (row, 2t+1); c2,c3 -> row+8
#pragma unroll
    for (int mi = 0; mi < 2; ++mi)
#pragma unroll
        for (int ni = 0; ni < 4; ++ni) {
            int rr = rowBase + wm + mi * 16 + g;
            int cc = colBase + wn + ni * 8 + t * 2;
            float b0 = bias[cc], b1 = bias[cc + 1];
            float2 v0 = make_float2((acc[mi][ni][0] + b0) * scale,
                                    (acc[mi][ni][1] + b1) * scale);
            float2 v1 = make_float2((acc[mi][ni][2] + b0) * scale,
                                    (acc[mi][ni][3] + b1) * scale);
            *reinterpret_cast<float2*>(C + (size_t)rr * 512 + cc) = v0;
            *reinterpret_cast<float2*>(C + (size_t)(rr + 8) * 512 + cc) = v1;
        }
}

__global__ __launch_bounds__(128) void qkv_gemm_tc_kernel(
    const float* __restrict__ qs, const float* __restrict__ ks,
    const float* __restrict__ vs,
    const float* __restrict__ Wq, const float* __restrict__ bq,
    const float* __restrict__ Wk, const float* __restrict__ bk,
    const float* __restrict__ Wv, const float* __restrict__ bv,
    float* __restrict__ oq, float* __restrict__ ok, float* __restrict__ ov)
{
    const int z = blockIdx.z;
    const float* A = (z == 0) ? qs : (z == 1) ? ks : vs;
    const float* W = (z == 0) ? Wq : (z == 1) ? Wk : Wv;
    const float* bias = (z == 0) ? bq : (z == 1) ? bk : bv;
    float* C = (z == 0) ? oq : (z == 1) ? ok : ov;
    const float scale = (z == 0) ? 0.125f : 1.0f;   // 1/sqrt(64)
    gemm512_tc_body(A, W, bias, C, scale, blockIdx.y * 64, blockIdx.x * 64);
}

__global__ __launch_bounds__(128) void out_gemm_tc_kernel(
    const float* __restrict__ A, const float* __restrict__ W,
    const float* __restrict__ bias, float* __restrict__ C)
{
    gemm512_tc_body(A, W, bias, C, 1.0f, blockIdx.y * 64, blockIdx.x * 64);
}

// ---------------------------------------------------------------------------
// Fused attention — round-5 structure (best: ~536us) with the dot product
// split into TWO interleaved FMA chains (halves dependency latency, +1 reg).
// One thread per query row, 128 threads/block. Grid: (Q/128, H, B).
// ---------------------------------------------------------------------------
__global__ __launch_bounds__(128) void attn_kernel(
    const float* __restrict__ qlocs, const float* __restrict__ klocs,
    const int* __restrict__ valid_lens)
{
    __shared__ __align__(16) float Ks[TK][DHh];
    __shared__ __align__(16) float Vs[TK][DHh];
    __shared__ float Ls[TK][2];
    __shared__ float Tb[NT];

    const int tid = threadIdx.x;
    const int h = blockIdx.y;
    const int b = blockIdx.z;
    const int qrow = blockIdx.x * 128 + tid;

#pragma unroll
    for (int i = 0; i < 4; ++i) {
        int v = (tid + i * 128) << 2;
        *reinterpret_cast<float4*>(&Tb[v]) =
            *reinterpret_cast<const float4*>(g_btab + h * NT + v);
    }

    const float qx = qlocs[(size_t)(b * Qq + qrow) * 2 + 0];
    const float qy = qlocs[(size_t)(b * Qq + qrow) * 2 + 1];
    const float inv_step = (float)(NT - 1) / DMAXV;

    float qv[DHh];
    const float* qptr = g_q + (size_t)(b * Qq + qrow) * DMm + h * DHh;
#pragma unroll
    for (int d = 0; d < DHh; d += 4) {
        float4 t = *reinterpret_cast<const float4*>(qptr + d);
        qv[d] = t.x; qv[d + 1] = t.y; qv[d + 2] = t.z; qv[d + 3] = t.w;
    }

    float acc[DHh];
#pragma unroll
    for (int d = 0; d < DHh; ++d) acc[d] = 0.f;
    float m = -CUDART_INF_F;
    float l = 0.f;

    const int kend = valid_lens[b];

    for (int kt0 = 0; kt0 < kend; kt0 += TK) {
        __syncthreads();
#pragma unroll
        for (int i = 0; i < 8; ++i) {
            int v = tid + i * 128;
            int r = v >> 4;
            int c = (v & 15) << 2;
            size_t base = (size_t)(b * Kk + kt0 + r) * DMm + h * DHh + c;
            *reinterpret_cast<float4*>(&Ks[r][c]) =
                *reinterpret_cast<const float4*>(g_k + base);
            *reinterpret_cast<float4*>(&Vs[r][c]) =
                *reinterpret_cast<const float4*>(g_v + base);
        }
        if (tid < TK * 2) {
            Ls[tid >> 1][tid & 1] = klocs[(size_t)(b * Kk + kt0) * 2 + tid];
        }
        __syncthreads();

        const int jmax = min(TK, kend - kt0);
        for (int j = 0; j < jmax; ++j) {
            float s0 = 0.f, s1 = 0.f;
#pragma unroll
            for (int d = 0; d < DHh; d += 2) {
                s0 = fmaf(qv[d], Ks[j][d], s0);
                s1 = fmaf(qv[d + 1], Ks[j][d + 1], s1);
            }
            float s = s0 + s1;

            // TISA RBF bias via LUT + linear interpolation
            float dx = qx - Ls[j][0];
            float dy = qy - Ls[j][1];
            float dist = sqrtf(fmaf(dx, dx, dy * dy));
            float t = dist * inv_step;
            int i0 = (int)t;
            i0 = min(i0, NT - 2);
            float frac = t - (float)i0;
            float b0 = Tb[i0];
            float b1 = Tb[i0 + 1];
            s += fmaf(frac, b1 - b0, b0);

            if (s > m) {
                float corr = __expf(m - s);
                l *= corr;
#pragma unroll
                for (int d = 0; d < DHh; ++d) acc[d] *= corr;
                m = s;
            }
            float p = __expf(s - m);
            l += p;
#pragma unroll
            for (int d = 0; d < DHh; ++d) acc[d] = fmaf(p, Vs[j][d], acc[d]);
        }
    }

    const float invl = 1.f / l;
    float* optr = g_ctx + (size_t)(b * Qq + qrow) * DMm + h * DHh;
#pragma unroll
    for (int d = 0; d < DHh; d += 4) {
        float4 t;
        t.x = acc[d] * invl;
        t.y = acc[d + 1] * invl;
        t.z = acc[d + 2] * invl;
        t.w = acc[d + 3] * invl;
        *reinterpret_cast<float4*>(optr + d) = t;
    }
}

// ---------------------------------------------------------------------------
// Launch
// ---------------------------------------------------------------------------
extern "C" void kernel_launch(void* const* d_in, const int* in_sizes, int n_in,
                              void* d_out, int out_size)
{
    const float* qs      = (const float*)d_in[0];
    const float* ks      = (const float*)d_in[1];
    const float* vs      = (const float*)d_in[2];
    const float* qs_locs = (const float*)d_in[3];
    const float* ks_locs = (const float*)d_in[4];
    const float* Wq      = (const float*)d_in[5];
    const float* bq      = (const float*)d_in[6];
    const float* Wk      = (const float*)d_in[7];
    const float* bk      = (const float*)d_in[8];
    const float* Wv      = (const float*)d_in[9];
    const float* bv      = (const float*)d_in[10];
    const float* Wo      = (const float*)d_in[11];
    const float* bo      = (const float*)d_in[12];
    const float* ap      = (const float*)d_in[13];
    const float* bp      = (const float*)d_in[14];
    const float* cp      = (const float*)d_in[15];
    const int*   vlen    = (const int*)d_in[16];
    float* out           = (float*)d_out;

    float *pq, *pk, *pv, *pctx;
    cudaGetSymbolAddress((void**)&pq,   g_q);
    cudaGetSymbolAddress((void**)&pk,   g_k);
    cudaGetSymbolAddress((void**)&pv,   g_v);
    cudaGetSymbolAddress((void**)&pctx, g_ctx);

    build_bias_table<<<Hh, 256>>>(ap, bp, cp);

    dim3 ggrid(512 / 64, (Bb * Qq) / 64, 3);  // (8, 64, 3)
    qkv_gemm_tc_kernel<<<ggrid, 128>>>(qs, ks, vs, Wq, bq, Wk, bk, Wv, bv,
                                       pq, pk, pv);

    dim3 agrid(Qq / 128, Hh, Bb);  // (16, 8, 2)
    attn_kernel<<<agrid, 128>>>(qs_locs, ks_locs, vlen);

    dim3 ogrid(512 / 64, (Bb * Qq) / 64);
    out_gemm_tc_kernel<<<ogrid, 128>>>(pctx, Wo, bo, out);
}

// round 9
// speedup vs baseline: 1.6415x; 1.6415x over previous
#include <cuda_runtime.h>
#include <math_constants.h>
#include <cstddef>
#include <cstdint>

// Problem constants
#define Bb 2
#define Qq 2048
#define Kk 2048
#define DMm 512
#define Hh 8
#define Ff 5
#define DHh 64

// Bias lookup table
#define NT 2048
#define DMAXV 14.15f

// smem paddings (bank-conflict-free fragment loads)
#define PADK 68
#define PADV 72

// Scratch (alloc-free rule: __device__ globals)
__device__ float g_q[Bb * Qq * DMm];
__device__ float g_k[Bb * Kk * DMm];
__device__ float g_v[Bb * Kk * DMm];
__device__ float g_ctx[Bb * Qq * DMm];
__device__ float g_btab[Hh * NT];

// ---------------------------------------------------------------------------
__device__ __forceinline__ float tf32_rna(float x) {
    uint32_t u;
    asm("cvt.rna.tf32.f32 %0, %1;" : "=r"(u) : "f"(x));
    return __uint_as_float(u);
}

__device__ __forceinline__ void mma_tf32(float* c,
    uint32_t a0, uint32_t a1, uint32_t a2, uint32_t a3,
    uint32_t b0, uint32_t b1)
{
    asm volatile(
        "mma.sync.aligned.m16n8k8.row.col.f32.tf32.tf32.f32 "
        "{%0,%1,%2,%3}, {%4,%5,%6,%7}, {%8,%9}, {%0,%1,%2,%3};"
        : "+f"(c[0]), "+f"(c[1]), "+f"(c[2]), "+f"(c[3])
        : "r"(a0), "r"(a1), "r"(a2), "r"(a3), "r"(b0), "r"(b1));
}

__device__ __forceinline__ void mma_tf32f(float* c,
    float a0, float a1, float a2, float a3, float b0, float b1)
{
    mma_tf32(c, __float_as_uint(a0), __float_as_uint(a1),
             __float_as_uint(a2), __float_as_uint(a3),
             __float_as_uint(b0), __float_as_uint(b1));
}

// ---------------------------------------------------------------------------
// Build per-head bias table
// ---------------------------------------------------------------------------
__global__ void build_bias_table(const float* __restrict__ apar,
                                 const float* __restrict__ bpar,
                                 const float* __restrict__ cpar)
{
    const int h = blockIdx.x;
    float af[Ff], bf[Ff], cf[Ff];
#pragma unroll
    for (int f = 0; f < Ff; ++f) {
        af[f] = apar[h * Ff + f];
        bf[f] = fabsf(bpar[h * Ff + f]);
        cf[f] = cpar[h * Ff + f];
    }
    const float step = DMAXV / (float)(NT - 1);
    for (int i = threadIdx.x; i < NT; i += blockDim.x) {
        float d = i * step;
        float s = 0.f;
#pragma unroll
        for (int f = 0; f < Ff; ++f) {
            float t = d - cf[f];
            s = fmaf(af[f], __expf(-bf[f] * t * t), s);
        }
        g_btab[h * NT + i] = s;
    }
}

// ---------------------------------------------------------------------------
// tf32 tensor-core GEMM with hi/lo split (validated round 7).
// ---------------------------------------------------------------------------
__device__ __forceinline__ void gemm512_tc_body(
    const float* __restrict__ A, const float* __restrict__ W,
    const float* __restrict__ bias, float* __restrict__ C, float scale,
    int rowBase, int colBase)
{
    __shared__ __align__(16) float Ah[64][20], Al[64][20];
    __shared__ __align__(16) float Bh[16][72], Bl[16][72];

    const int tid = threadIdx.x;
    const int lane = tid & 31;
    const int warp = tid >> 5;
    const int wm = (warp & 1) * 32;
    const int wn = (warp >> 1) * 32;
    const int g = lane >> 2;
    const int t = lane & 3;

    float acc[2][4][4];
#pragma unroll
    for (int mi = 0; mi < 2; ++mi)
#pragma unroll
        for (int ni = 0; ni < 4; ++ni)
#pragma unroll
            for (int e = 0; e < 4; ++e) acc[mi][ni][e] = 0.f;

    const int arow = tid >> 2;
    const int acol = (tid & 3) << 2;
    const int brow = tid >> 4;
    const int bcol = (tid & 15) << 2;

    for (int k0 = 0; k0 < 512; k0 += 16) {
        __syncthreads();
#pragma unroll
        for (int p = 0; p < 2; ++p) {
            float4 va = *reinterpret_cast<const float4*>(
                A + (size_t)(rowBase + arow + p * 32) * 512 + k0 + acol);
            float4 hA, lA;
            hA.x = tf32_rna(va.x); lA.x = tf32_rna(va.x - hA.x);
            hA.y = tf32_rna(va.y); lA.y = tf32_rna(va.y - hA.y);
            hA.z = tf32_rna(va.z); lA.z = tf32_rna(va.z - hA.z);
            hA.w = tf32_rna(va.w); lA.w = tf32_rna(va.w - hA.w);
            *reinterpret_cast<float4*>(&Ah[arow + p * 32][acol]) = hA;
            *reinterpret_cast<float4*>(&Al[arow + p * 32][acol]) = lA;

            float4 vb = *reinterpret_cast<const float4*>(
                W + (size_t)(k0 + brow + p * 8) * 512 + colBase + bcol);
            float4 hB, lB;
            hB.x = tf32_rna(vb.x); lB.x = tf32_rna(vb.x - hB.x);
            hB.y = tf32_rna(vb.y); lB.y = tf32_rna(vb.y - hB.y);
            hB.z = tf32_rna(vb.z); lB.z = tf32_rna(vb.z - hB.z);
            hB.w = tf32_rna(vb.w); lB.w = tf32_rna(vb.w - hB.w);
            *reinterpret_cast<float4*>(&Bh[brow + p * 8][bcol]) = hB;
            *reinterpret_cast<float4*>(&Bl[brow + p * 8][bcol]) = lB;
        }
        __syncthreads();

#pragma unroll
        for (int kk = 0; kk < 16; kk += 8) {
            uint32_t ah[2][4], al[2][4];
#pragma unroll
            for (int mi = 0; mi < 2; ++mi) {
                int r0 = wm + mi * 16 + g;
                ah[mi][0] = __float_as_uint(Ah[r0][kk + t]);
                ah[mi][1] = __float_as_uint(Ah[r0 + 8][kk + t]);
                ah[mi][2] = __float_as_uint(Ah[r0][kk + t + 4]);
                ah[mi][3] = __float_as_uint(Ah[r0 + 8][kk + t + 4]);
                al[mi][0] = __float_as_uint(Al[r0][kk + t]);
                al[mi][1] = __float_as_uint(Al[r0 + 8][kk + t]);
                al[mi][2] = __float_as_uint(Al[r0][kk + t + 4]);
                al[mi][3] = __float_as_uint(Al[r0 + 8][kk + t + 4]);
            }
            uint32_t bh[4][2], bl[4][2];
#pragma unroll
            for (int ni = 0; ni < 4; ++ni) {
                int c0 = wn + ni * 8 + g;
                bh[ni][0] = __float_as_uint(Bh[kk + t][c0]);
                bh[ni][1] = __float_as_uint(Bh[kk + t + 4][c0]);
                bl[ni][0] = __float_as_uint(Bl[kk + t][c0]);
                bl[ni][1] = __float_as_uint(Bl[kk + t + 4][c0]);
            }
#pragma unroll
            for (int mi = 0; mi < 2; ++mi)
#pragma unroll
                for (int ni = 0; ni < 4; ++ni) {
                    mma_tf32(acc[mi][ni], ah[mi][0], ah[mi][1], ah[mi][2], ah[mi][3],
                             bh[ni][0], bh[ni][1]);
                    mma_tf32(acc[mi][ni], ah[mi][0], ah[mi][1], ah[mi][2], ah[mi][3],
                             bl[ni][0], bl[ni][1]);
                    mma_tf32(acc[mi][ni], al[mi][0], al[mi][1], al[mi][2], al[mi][3],
                             bh[ni][0], bh[ni][1]);
                }
        }
    }

#pragma unroll
    for (int mi = 0; mi < 2; ++mi)
#pragma unroll
        for (int ni = 0; ni < 4; ++ni) {
            int rr = rowBase + wm + mi * 16 + g;
            int cc = colBase + wn + ni * 8 + t * 2;
            float b0 = bias[cc], b1 = bias[cc + 1];
            float2 v0 = make_float2((acc[mi][ni][0] + b0) * scale,
                                    (acc[mi][ni][1] + b1) * scale);
            float2 v1 = make_float2((acc[mi][ni][2] + b0) * scale,
                                    (acc[mi][ni][3] + b1) * scale);
            *reinterpret_cast<float2*>(C + (size_t)rr * 512 + cc) = v0;
            *reinterpret_cast<float2*>(C + (size_t)(rr + 8) * 512 + cc) = v1;
        }
}

__global__ __launch_bounds__(128) void qkv_gemm_tc_kernel(
    const float* __restrict__ qs, const float* __restrict__ ks,
    const float* __restrict__ vs,
    const float* __restrict__ Wq, const float* __restrict__ bq,
    const float* __restrict__ Wk, const float* __restrict__ bk,
    const float* __restrict__ Wv, const float* __restrict__ bv,
    float* __restrict__ oq, float* __restrict__ ok, float* __restrict__ ov)
{
    const int z = blockIdx.z;
    const float* A = (z == 0) ? qs : (z == 1) ? ks : vs;
    const float* W = (z == 0) ? Wq : (z == 1) ? Wk : Wv;
    const float* bias = (z == 0) ? bq : (z == 1) ? bk : bv;
    float* C = (z == 0) ? oq : (z == 1) ? ok : ov;
    const float scale = (z == 0) ? 0.125f : 1.0f;
    gemm512_tc_body(A, W, bias, C, scale, blockIdx.y * 64, blockIdx.x * 64);
}

__global__ __launch_bounds__(128) void out_gemm_tc_kernel(
    const float* __restrict__ A, const float* __restrict__ W,
    const float* __restrict__ bias, float* __restrict__ C)
{
    gemm512_tc_body(A, W, bias, C, 1.0f, blockIdx.y * 64, blockIdx.x * 64);
}

// ---------------------------------------------------------------------------
// Bias + exp helper for one score element
// ---------------------------------------------------------------------------
__device__ __forceinline__ float score_to_p(
    float s, float qx, float qy, float kx, float ky, bool valid,
    const float* __restrict__ Tb, float inv_step)
{
    float dx = qx - kx, dy = qy - ky;
    float d2 = fmaf(dx, dx, dy * dy);
    d2 = fmaxf(d2, 1e-20f);
    float dist = d2 * rsqrtf(d2);
    float tt = dist * inv_step;
    int i0 = min((int)tt, NT - 2);
    float frac = tt - (float)i0;
    float b0 = Tb[i0], b1 = Tb[i0 + 1];
    s += fmaf(frac, b1 - b0, b0);
    s = valid ? s : -1e30f;      // exp -> 0 for masked keys
    return __expf(s);
}

// ---------------------------------------------------------------------------
// MMA flash attention. Block = (64 q rows, one (b,h)); 4 warps x 16 rows.
// Scores are bounded (|s| <~ 16), so raw exp(s) + end normalization is the
// exact softmax — no running max needed.
// ---------------------------------------------------------------------------
__global__ __launch_bounds__(128) void attn_mma_kernel(
    const float* __restrict__ qlocs, const float* __restrict__ klocs,
    const int* __restrict__ valid_lens)
{
    extern __shared__ float sm[];
    float* Khi = sm;                       // 64*PADK
    float* Klo = Khi + 64 * PADK;
    float* Vhi = Klo + 64 * PADK;          // 64*PADV
    float* Vlo = Vhi + 64 * PADV;
    float* Pm  = Vlo + 64 * PADV;          // 64*PADK
    float* Tb  = Pm  + 64 * PADK;          // NT
    float* Lk  = Tb  + NT;                 // 128

    const int tid = threadIdx.x;
    const int lane = tid & 31;
    const int warp = tid >> 5;
    const int g = lane >> 2;
    const int t = lane & 3;
    const int h = blockIdx.y;
    const int b = blockIdx.z;
    const int qbase = blockIdx.x * 64 + warp * 16;
    const int row0 = qbase + g;
    const int row1 = row0 + 8;

    // Bias table -> smem
#pragma unroll
    for (int i = 0; i < 4; ++i) {
        int v = (tid + i * 128) << 2;
        *reinterpret_cast<float4*>(&Tb[v]) =
            *reinterpret_cast<const float4*>(g_btab + h * NT + v);
    }

    // Q A-fragments (hi/lo), resident for the whole kernel
    float qh[8][4], ql[8][4];
    {
        const float* q0 = g_q + (size_t)(b * Qq + row0) * DMm + h * DHh;
        const float* q1 = g_q + (size_t)(b * Qq + row1) * DMm + h * DHh;
#pragma unroll
        for (int k0 = 0; k0 < 8; ++k0) {
            float v0 = q0[8 * k0 + t];
            float v1 = q1[8 * k0 + t];
            float v2 = q0[8 * k0 + t + 4];
            float v3 = q1[8 * k0 + t + 4];
            qh[k0][0] = tf32_rna(v0); ql[k0][0] = tf32_rna(v0 - qh[k0][0]);
            qh[k0][1] = tf32_rna(v1); ql[k0][1] = tf32_rna(v1 - qh[k0][1]);
            qh[k0][2] = tf32_rna(v2); ql[k0][2] = tf32_rna(v2 - qh[k0][2]);
            qh[k0][3] = tf32_rna(v3); ql[k0][3] = tf32_rna(v3 - qh[k0][3]);
        }
    }
    const float qx0 = qlocs[(size_t)(b * Qq + row0) * 2 + 0];
    const float qy0 = qlocs[(size_t)(b * Qq + row0) * 2 + 1];
    const float qx1 = qlocs[(size_t)(b * Qq + row1) * 2 + 0];
    const float qy1 = qlocs[(size_t)(b * Qq + row1) * 2 + 1];
    const float inv_step = (float)(NT - 1) / DMAXV;

    float o[8][4];
#pragma unroll
    for (int n = 0; n < 8; ++n)
#pragma unroll
        for (int e = 0; e < 4; ++e) o[n][e] = 0.f;
    float l0 = 0.f, l1 = 0.f;

    const int kend = valid_lens[b];

    for (int kt0 = 0; kt0 < kend; kt0 += 64) {
        __syncthreads();
        // Fill K/V tiles (hi/lo split at fill time) + key locations
#pragma unroll
        for (int p = 0; p < 8; ++p) {
            int idx = tid + p * 128;
            int r = idx >> 4;
            int c = (idx & 15) << 2;
            size_t gb = (size_t)(b * Kk + kt0 + r) * DMm + h * DHh + c;
            float4 kv = *reinterpret_cast<const float4*>(g_k + gb);
            float4 kh, kl;
            kh.x = tf32_rna(kv.x); kl.x = tf32_rna(kv.x - kh.x);
            kh.y = tf32_rna(kv.y); kl.y = tf32_rna(kv.y - kh.y);
            kh.z = tf32_rna(kv.z); kl.z = tf32_rna(kv.z - kh.z);
            kh.w = tf32_rna(kv.w); kl.w = tf32_rna(kv.w - kh.w);
            *reinterpret_cast<float4*>(&Khi[r * PADK + c]) = kh;
            *reinterpret_cast<float4*>(&Klo[r * PADK + c]) = kl;
            float4 vv = *reinterpret_cast<const float4*>(g_v + gb);
            float4 vh, vl;
            vh.x = tf32_rna(vv.x); vl.x = tf32_rna(vv.x - vh.x);
            vh.y = tf32_rna(vv.y); vl.y = tf32_rna(vv.y - vh.y);
            vh.z = tf32_rna(vv.z); vl.z = tf32_rna(vv.z - vh.z);
            vh.w = tf32_rna(vv.w); vl.w = tf32_rna(vv.w - vh.w);
            *reinterpret_cast<float4*>(&Vhi[r * PADV + c]) = vh;
            *reinterpret_cast<float4*>(&Vlo[r * PADV + c]) = vl;
        }
        Lk[tid] = klocs[(size_t)(b * Kk + kt0) * 2 + tid];
        __syncthreads();

        // S = Q . K^T (split tf32: hh + hl + lh)
        float cc[8][4];
#pragma unroll
        for (int n = 0; n < 8; ++n)
#pragma unroll
            for (int e = 0; e < 4; ++e) cc[n][e] = 0.f;

#pragma unroll
        for (int k0 = 0; k0 < 8; ++k0) {
            int ka = 8 * k0 + t;
#pragma unroll
            for (int n = 0; n < 8; ++n) {
                int krow = (8 * n + g) * PADK;
                float bh0 = Khi[krow + ka];
                float bh1 = Khi[krow + ka + 4];
                float bl0 = Klo[krow + ka];
                float bl1 = Klo[krow + ka + 4];
                mma_tf32f(cc[n], qh[k0][0], qh[k0][1], qh[k0][2], qh[k0][3], bh0, bh1);
                mma_tf32f(cc[n], qh[k0][0], qh[k0][1], qh[k0][2], qh[k0][3], bl0, bl1);
                mma_tf32f(cc[n], ql[k0][0], ql[k0][1], ql[k0][2], ql[k0][3], bh0, bh1);
            }
        }

        // bias + mask + exp, accumulate row sums, stage P to smem
#pragma unroll
        for (int n = 0; n < 8; ++n) {
            int klocal = 8 * n + 2 * t;
            float kxA = Lk[klocal * 2 + 0];
            float kyA = Lk[klocal * 2 + 1];
            float kxB = Lk[klocal * 2 + 2];
            float kyB = Lk[klocal * 2 + 3];
            bool vA = (kt0 + klocal) < kend;
            bool vB = (kt0 + klocal + 1) < kend;
            cc[n][0] = score_to_p(cc[n][0], qx0, qy0, kxA, kyA, vA, Tb, inv_step);
            cc[n][1] = score_to_p(cc[n][1], qx0, qy0, kxB, kyB, vB, Tb, inv_step);
            cc[n][2] = score_to_p(cc[n][2], qx1, qy1, kxA, kyA, vA, Tb, inv_step);
            cc[n][3] = score_to_p(cc[n][3], qx1, qy1, kxB, kyB, vB, Tb, inv_step);
            l0 += cc[n][0] + cc[n][1];
            l1 += cc[n][2] + cc[n][3];
            *reinterpret_cast<float2*>(&Pm[(16 * warp + g) * PADK + klocal]) =
                make_float2(cc[n][0], cc[n][1]);
            *reinterpret_cast<float2*>(&Pm[(16 * warp + g + 8) * PADK + klocal]) =
                make_float2(cc[n][2], cc[n][3]);
        }
        __syncwarp();

        // O += P . V (split tf32)
#pragma unroll
        for (int k0 = 0; k0 < 8; ++k0) {
            int ka = 8 * k0 + t;
            float pa0 = Pm[(16 * warp + g) * PADK + ka];
            float pa1 = Pm[(16 * warp + g + 8) * PADK + ka];
            float pa2 = Pm[(16 * warp + g) * PADK + ka + 4];
            float pa3 = Pm[(16 * warp + g + 8) * PADK + ka + 4];
            float ph0 = tf32_rna(pa0), pl0 = tf32_rna(pa0 - ph0);
            float ph1 = tf32_rna(pa1), pl1 = tf32_rna(pa1 - ph1);
            float ph2 = tf32_rna(pa2), pl2 = tf32_rna(pa2 - ph2);
            float ph3 = tf32_rna(pa3), pl3 = tf32_rna(pa3 - ph3);
#pragma unroll
            for (int n = 0; n < 8; ++n) {
                int vcol = 8 * n + g;
                float vh0 = Vhi[ka * PADV + vcol];
                float vh1 = Vhi[(ka + 4) * PADV + vcol];
                float vl0 = Vlo[ka * PADV + vcol];
                float vl1 = Vlo[(ka + 4) * PADV + vcol];
                mma_tf32f(o[n], ph0, ph1, ph2, ph3, vh0, vh1);
                mma_tf32f(o[n], ph0, ph1, ph2, ph3, vl0, vl1);
                mma_tf32f(o[n], pl0, pl1, pl2, pl3, vh0, vh1);
            }
        }
    }

    // Finalize: reduce row sums across the quad, normalize, write ctx
    l0 += __shfl_xor_sync(0xffffffffu, l0, 1);
    l0 += __shfl_xor_sync(0xffffffffu, l0, 2);
    l1 += __shfl_xor_sync(0xffffffffu, l1, 1);
    l1 += __shfl_xor_sync(0xffffffffu, l1, 2);
    const float i0 = 1.f / l0;
    const float i1 = 1.f / l1;

    float* c0p = g_ctx + (size_t)(b * Qq + row0) * DMm + h * DHh;
    float* c1p = g_ctx + (size_t)(b * Qq + row1) * DMm + h * DHh;
#pragma unroll
    for (int n = 0; n < 8; ++n) {
        int cc2 = 8 * n + 2 * t;
        *reinterpret_cast<float2*>(c0p + cc2) =
            make_float2(o[n][0] * i0, o[n][1] * i0);
        *reinterpret_cast<float2*>(c1p + cc2) =
            make_float2(o[n][2] * i1, o[n][3] * i1);
    }
}

// ---------------------------------------------------------------------------
// Launch (no static guards — deterministic, identical behavior every call)
// ---------------------------------------------------------------------------
#define ATTN_SMEM ((64 * PADK * 3 + 64 * PADV * 2 + NT + 128) * 4)

extern "C" void kernel_launch(void* const* d_in, const int* in_sizes, int n_in,
                              void* d_out, int out_size)
{
    const float* qs      = (const float*)d_in[0];
    const float* ks      = (const float*)d_in[1];
    const float* vs      = (const float*)d_in[2];
    const float* qs_locs = (const float*)d_in[3];
    const float* ks_locs = (const float*)d_in[4];
    const float* Wq      = (const float*)d_in[5];
    const float* bq      = (const float*)d_in[6];
    const float* Wk      = (const float*)d_in[7];
    const float* bk      = (const float*)d_in[8];
    const float* Wv      = (const float*)d_in[9];
    const float* bv      = (const float*)d_in[10];
    const float* Wo      = (const float*)d_in[11];
    const float* bo      = (const float*)d_in[12];
    const float* ap      = (const float*)d_in[13];
    const float* bp      = (const float*)d_in[14];
    const float* cp      = (const float*)d_in[15];
    const int*   vlen    = (const int*)d_in[16];
    float* out           = (float*)d_out;

    float *pq, *pk, *pv, *pctx;
    cudaGetSymbolAddress((void**)&pq,   g_q);
    cudaGetSymbolAddress((void**)&pk,   g_k);
    cudaGetSymbolAddress((void**)&pv,   g_v);
    cudaGetSymbolAddress((void**)&pctx, g_ctx);

    cudaFuncSetAttribute(attn_mma_kernel,
                         cudaFuncAttributeMaxDynamicSharedMemorySize,
                         ATTN_SMEM);

    build_bias_table<<<Hh, 256>>>(ap, bp, cp);

    dim3 ggrid(512 / 64, (Bb * Qq) / 64, 3);
    qkv_gemm_tc_kernel<<<ggrid, 128>>>(qs, ks, vs, Wq, bq, Wk, bk, Wv, bv,
                                       pq, pk, pv);

    dim3 agrid(Qq / 64, Hh, Bb);  // (32, 8, 2)
    attn_mma_kernel<<<agrid, 128, ATTN_SMEM>>>(qs_locs, ks_locs, vlen);

    dim3 ogrid(512 / 64, (Bb * Qq) / 64);
    out_gemm_tc_kernel<<<ogrid, 128>>>(pctx, Wo, bo, out);
}

// round 13
// speedup vs baseline: 1.7954x; 1.0938x over previous
#include <cuda_runtime.h>
#include <math_constants.h>
#include <cstddef>
#include <cstdint>

// Problem constants
#define Bb 2
#define Qq 2048
#define Kk 2048
#define DMm 512
#define Hh 8
#define Ff 5
#define DHh 64

// Bias lookup table
#define NT 2048
#define DMAXV 14.15f

// smem paddings: stride ≡ 8 (mod 32) -> conflict-free float2 fragment loads
#define PADK 72
#define PADV 72

// Scratch (alloc-free rule: __device__ globals)
__device__ float g_q[Bb * Qq * DMm];
__device__ float g_k[Bb * Kk * DMm];
__device__ float g_v[Bb * Kk * DMm];
__device__ float g_ctx[Bb * Qq * DMm];
__device__ float g_btab[Hh * NT];

// ---------------------------------------------------------------------------
__device__ __forceinline__ float tf32_rna(float x) {
    uint32_t u;
    asm("cvt.rna.tf32.f32 %0, %1;" : "=r"(u) : "f"(x));
    return __uint_as_float(u);
}

__device__ __forceinline__ void mma_tf32(float* c,
    uint32_t a0, uint32_t a1, uint32_t a2, uint32_t a3,
    uint32_t b0, uint32_t b1)
{
    asm volatile(
        "mma.sync.aligned.m16n8k8.row.col.f32.tf32.tf32.f32 "
        "{%0,%1,%2,%3}, {%4,%5,%6,%7}, {%8,%9}, {%0,%1,%2,%3};"
        : "+f"(c[0]), "+f"(c[1]), "+f"(c[2]), "+f"(c[3])
        : "r"(a0), "r"(a1), "r"(a2), "r"(a3), "r"(b0), "r"(b1));
}

__device__ __forceinline__ void mma_tf32f(float* c,
    float a0, float a1, float a2, float a3, float b0, float b1)
{
    mma_tf32(c, __float_as_uint(a0), __float_as_uint(a1),
             __float_as_uint(a2), __float_as_uint(a3),
             __float_as_uint(b0), __float_as_uint(b1));
}

// ---------------------------------------------------------------------------
// Build per-head bias table
// ---------------------------------------------------------------------------
__global__ void build_bias_table(const float* __restrict__ apar,
                                 const float* __restrict__ bpar,
                                 const float* __restrict__ cpar)
{
    const int h = blockIdx.x;
    float af[Ff], bf[Ff], cf[Ff];
#pragma unroll
    for (int f = 0; f < Ff; ++f) {
        af[f] = apar[h * Ff + f];
        bf[f] = fabsf(bpar[h * Ff + f]);
        cf[f] = cpar[h * Ff + f];
    }
    const float step = DMAXV / (float)(NT - 1);
    for (int i = threadIdx.x; i < NT; i += blockDim.x) {
        float d = i * step;
        float s = 0.f;
#pragma unroll
        for (int f = 0; f < Ff; ++f) {
            float t = d - cf[f];
            s = fmaf(af[f], __expf(-bf[f] * t * t), s);
        }
        g_btab[h * NT + i] = s;
    }
}

// ---------------------------------------------------------------------------
// tf32 tensor-core GEMM with hi/lo split (validated round 7/9 - unchanged).
// ---------------------------------------------------------------------------
__device__ __forceinline__ void gemm512_tc_body(
    const float* __restrict__ A, const float* __restrict__ W,
    const float* __restrict__ bias, float* __restrict__ C, float scale,
    int rowBase, int colBase)
{
    __shared__ __align__(16) float Ah[64][20], Al[64][20];
    __shared__ __align__(16) float Bh[16][72], Bl[16][72];

    const int tid = threadIdx.x;
    const int lane = tid & 31;
    const int warp = tid >> 5;
    const int wm = (warp & 1) * 32;
    const int wn = (warp >> 1) * 32;
    const int g = lane >> 2;
    const int t = lane & 3;

    float acc[2][4][4];
#pragma unroll
    for (int mi = 0; mi < 2; ++mi)
#pragma unroll
        for (int ni = 0; ni < 4; ++ni)
#pragma unroll
            for (int e = 0; e < 4; ++e) acc[mi][ni][e] = 0.f;

    const int arow = tid >> 2;
    const int acol = (tid & 3) << 2;
    const int brow = tid >> 4;
    const int bcol = (tid & 15) << 2;

    for (int k0 = 0; k0 < 512; k0 += 16) {
        __syncthreads();
#pragma unroll
        for (int p = 0; p < 2; ++p) {
            float4 va = *reinterpret_cast<const float4*>(
                A + (size_t)(rowBase + arow + p * 32) * 512 + k0 + acol);
            float4 hA, lA;
            hA.x = tf32_rna(va.x); lA.x = tf32_rna(va.x - hA.x);
            hA.y = tf32_rna(va.y); lA.y = tf32_rna(va.y - hA.y);
            hA.z = tf32_rna(va.z); lA.z = tf32_rna(va.z - hA.z);
            hA.w = tf32_rna(va.w); lA.w = tf32_rna(va.w - hA.w);
            *reinterpret_cast<float4*>(&Ah[arow + p * 32][acol]) = hA;
            *reinterpret_cast<float4*>(&Al[arow + p * 32][acol]) = lA;

            float4 vb = *reinterpret_cast<const float4*>(
                W + (size_t)(k0 + brow + p * 8) * 512 + colBase + bcol);
            float4 hB, lB;
            hB.x = tf32_rna(vb.x); lB.x = tf32_rna(vb.x - hB.x);
            hB.y = tf32_rna(vb.y); lB.y = tf32_rna(vb.y - hB.y);
            hB.z = tf32_rna(vb.z); lB.z = tf32_rna(vb.z - hB.z);
            hB.w = tf32_rna(vb.w); lB.w = tf32_rna(vb.w - hB.w);
            *reinterpret_cast<float4*>(&Bh[brow + p * 8][bcol]) = hB;
            *reinterpret_cast<float4*>(&Bl[brow + p * 8][bcol]) = lB;
        }
        __syncthreads();

#pragma unroll
        for (int kk = 0; kk < 16; kk += 8) {
            uint32_t ah[2][4], al[2][4];
#pragma unroll
            for (int mi = 0; mi < 2; ++mi) {
                int r0 = wm + mi * 16 + g;
                ah[mi][0] = __float_as_uint(Ah[r0][kk + t]);
                ah[mi][1] = __float_as_uint(Ah[r0 + 8][kk + t]);
                ah[mi][2] = __float_as_uint(Ah[r0][kk + t + 4]);
                ah[mi][3] = __float_as_uint(Ah[r0 + 8][kk + t + 4]);
                al[mi][0] = __float_as_uint(Al[r0][kk + t]);
                al[mi][1] = __float_as_uint(Al[r0 + 8][kk + t]);
                al[mi][2] = __float_as_uint(Al[r0][kk + t + 4]);
                al[mi][3] = __float_as_uint(Al[r0 + 8][kk + t + 4]);
            }
            uint32_t bh[4][2], bl[4][2];
#pragma unroll
            for (int ni = 0; ni < 4; ++ni) {
                int c0 = wn + ni * 8 + g;
                bh[ni][0] = __float_as_uint(Bh[kk + t][c0]);
                bh[ni][1] = __float_as_uint(Bh[kk + t + 4][c0]);
                bl[ni][0] = __float_as_uint(Bl[kk + t][c0]);
                bl[ni][1] = __float_as_uint(Bl[kk + t + 4][c0]);
            }
#pragma unroll
            for (int mi = 0; mi < 2; ++mi)
#pragma unroll
                for (int ni = 0; ni < 4; ++ni) {
                    mma_tf32(acc[mi][ni], ah[mi][0], ah[mi][1], ah[mi][2], ah[mi][3],
                             bh[ni][0], bh[ni][1]);
                    mma_tf32(acc[mi][ni], ah[mi][0], ah[mi][1], ah[mi][2], ah[mi][3],
                             bl[ni][0], bl[ni][1]);
                    mma_tf32(acc[mi][ni], al[mi][0], al[mi][1], al[mi][2], al[mi][3],
                             bh[ni][0], bh[ni][1]);
                }
        }
    }

#pragma unroll
    for (int mi = 0; mi < 2; ++mi)
#pragma unroll
        for (int ni = 0; ni < 4; ++ni) {
            int rr = rowBase + wm + mi * 16 + g;
            int cc = colBase + wn + ni * 8 + t * 2;
            float b0 = bias[cc], b1 = bias[cc + 1];
            float2 v0 = make_float2((acc[mi][ni][0] + b0) * scale,
                                    (acc[mi][ni][1] + b1) * scale);
            float2 v1 = make_float2((acc[mi][ni][2] + b0) * scale,
                                    (acc[mi][ni][3] + b1) * scale);
            *reinterpret_cast<float2*>(C + (size_t)rr * 512 + cc) = v0;
            *reinterpret_cast<float2*>(C + (size_t)(rr + 8) * 512 + cc) = v1;
        }
}

__global__ __launch_bounds__(128) void qkv_gemm_tc_kernel(
    const float* __restrict__ qs, const float* __restrict__ ks,
    const float* __restrict__ vs,
    const float* __restrict__ Wq, const float* __restrict__ bq,
    const float* __restrict__ Wk, const float* __restrict__ bk,
    const float* __restrict__ Wv, const float* __restrict__ bv,
    float* __restrict__ oq, float* __restrict__ ok, float* __restrict__ ov)
{
    const int z = blockIdx.z;
    const float* A = (z == 0) ? qs : (z == 1) ? ks : vs;
    const float* W = (z == 0) ? Wq : (z == 1) ? Wk : Wv;
    const float* bias = (z == 0) ? bq : (z == 1) ? bk : bv;
    float* C = (z == 0) ? oq : (z == 1) ? ok : ov;
    const float scale = (z == 0) ? 0.125f : 1.0f;
    gemm512_tc_body(A, W, bias, C, scale, blockIdx.y * 64, blockIdx.x * 64);
}

__global__ __launch_bounds__(128) void out_gemm_tc_kernel(
    const float* __restrict__ A, const float* __restrict__ W,
    const float* __restrict__ bias, float* __restrict__ C)
{
    gemm512_tc_body(A, W, bias, C, 1.0f, blockIdx.y * 64, blockIdx.x * 64);
}

// ---------------------------------------------------------------------------
// Bias + exp helper for one score element
// ---------------------------------------------------------------------------
__device__ __forceinline__ float score_to_p(
    float s, float qx, float qy, float kx, float ky, bool valid,
    const float* __restrict__ Tb, float inv_step)
{
    float dx = qx - kx, dy = qy - ky;
    float d2 = fmaf(dx, dx, dy * dy);
    d2 = fmaxf(d2, 1e-20f);
    float dist = d2 * rsqrtf(d2);
    float tt = dist * inv_step;
    int i0 = min((int)tt, NT - 2);
    float frac = tt - (float)i0;
    float b0 = Tb[i0], b1 = Tb[i0 + 1];
    s += fmaf(frac, b1 - b0, b0);
    s = valid ? s : -1e30f;      // exp -> 0 for masked keys
    return __expf(s);
}

// ---------------------------------------------------------------------------
// MMA flash attention, 256 threads (8 warps x 16 q rows = 128 q rows/CTA).
// K stored with permuted columns so each B-fragment pair (t, t+4) is one
// float2 (LDS.64). Grid: (Q/128, H, B).
// ---------------------------------------------------------------------------
__global__ __launch_bounds__(256) void attn_mma_kernel(
    const float* __restrict__ qlocs, const float* __restrict__ klocs,
    const int* __restrict__ valid_lens)
{
    extern __shared__ float sm[];
    float* Khi = sm;                       // 64*PADK (permuted cols)
    float* Klo = Khi + 64 * PADK;
    float* Vhi = Klo + 64 * PADK;          // 64*PADV (plain layout)
    float* Vlo = Vhi + 64 * PADV;
    float* Pm  = Vlo + 64 * PADV;          // 128*PADK
    float* Tb  = Pm  + 128 * PADK;         // NT
    float* Lk  = Tb  + NT;                 // 128

    const int tid = threadIdx.x;
    const int lane = tid & 31;
    const int warp = tid >> 5;             // 0..7
    const int g = lane >> 2;
    const int t = lane & 3;
    const int h = blockIdx.y;
    const int b = blockIdx.z;
    const int row0 = blockIdx.x * 128 + warp * 16 + g;
    const int row1 = row0 + 8;

    // Bias table -> smem (2048 floats, 256 threads -> 2 float4 each)
#pragma unroll
    for (int i = 0; i < 2; ++i) {
        int v = (tid + i * 256) << 2;
        *reinterpret_cast<float4*>(&Tb[v]) =
            *reinterpret_cast<const float4*>(g_btab + h * NT + v);
    }

    // Q A-fragments (hi/lo), resident for the whole kernel
    float qh[8][4], ql[8][4];
    {
        const float* q0 = g_q + (size_t)(b * Qq + row0) * DMm + h * DHh;
        const float* q1 = g_q + (size_t)(b * Qq + row1) * DMm + h * DHh;
#pragma unroll
        for (int k0 = 0; k0 < 8; ++k0) {
            float v0 = q0[8 * k0 + t];
            float v1 = q1[8 * k0 + t];
            float v2 = q0[8 * k0 + t + 4];
            float v3 = q1[8 * k0 + t + 4];
            qh[k0][0] = tf32_rna(v0); ql[k0][0] = tf32_rna(v0 - qh[k0][0]);
            qh[k0][1] = tf32_rna(v1); ql[k0][1] = tf32_rna(v1 - qh[k0][1]);
            qh[k0][2] = tf32_rna(v2); ql[k0][2] = tf32_rna(v2 - qh[k0][2]);
            qh[k0][3] = tf32_rna(v3); ql[k0][3] = tf32_rna(v3 - qh[k0][3]);
        }
    }
    const float qx0 = qlocs[(size_t)(b * Qq + row0) * 2 + 0];
    const float qy0 = qlocs[(size_t)(b * Qq + row0) * 2 + 1];
    const float qx1 = qlocs[(size_t)(b * Qq + row1) * 2 + 0];
    const float qy1 = qlocs[(size_t)(b * Qq + row1) * 2 + 1];
    const float inv_step = (float)(NT - 1) / DMAXV;

    float o[8][4];
#pragma unroll
    for (int n = 0; n < 8; ++n)
#pragma unroll
        for (int e = 0; e < 4; ++e) o[n][e] = 0.f;
    float l0 = 0.f, l1 = 0.f;

    const int kend = valid_lens[b];

    for (int kt0 = 0; kt0 < kend; kt0 += 64) {
        __syncthreads();

        // --- K fill with column permutation (pairs (p, p+4) adjacent) ---
        // 512 tasks = 64 rows x 8 groups; 256 threads -> 2 each.
#pragma unroll
        for (int i = 0; i < 2; ++i) {
            int task = tid + i * 256;
            int r = task >> 3;
            int k0 = task & 7;
            size_t gb = (size_t)(b * Kk + kt0 + r) * DMm + h * DHh + 8 * k0;
            float4 a = *reinterpret_cast<const float4*>(g_k + gb);
            float4 c = *reinterpret_cast<const float4*>(g_k + gb + 4);
            float4 ah, alo, ch, clo;
            ah.x = tf32_rna(a.x); alo.x = tf32_rna(a.x - ah.x);
            ah.y = tf32_rna(a.y); alo.y = tf32_rna(a.y - ah.y);
            ah.z = tf32_rna(a.z); alo.z = tf32_rna(a.z - ah.z);
            ah.w = tf32_rna(a.w); alo.w = tf32_rna(a.w - ah.w);
            ch.x = tf32_rna(c.x); clo.x = tf32_rna(c.x - ch.x);
            ch.y = tf32_rna(c.y); clo.y = tf32_rna(c.y - ch.y);
            ch.z = tf32_rna(c.z); clo.z = tf32_rna(c.z - ch.z);
            ch.w = tf32_rna(c.w); clo.w = tf32_rna(c.w - ch.w);
            // permuted: col' 8k0+{0,2,4,6} = pos {0..3}; +{1,3,5,7} = pos {4..7}
            *reinterpret_cast<float4*>(&Khi[r * PADK + 8 * k0]) =
                make_float4(ah.x, ch.x, ah.y, ch.y);
            *reinterpret_cast<float4*>(&Khi[r * PADK + 8 * k0 + 4]) =
                make_float4(ah.z, ch.z, ah.w, ch.w);
            *reinterpret_cast<float4*>(&Klo[r * PADK + 8 * k0]) =
                make_float4(alo.x, clo.x, alo.y, clo.y);
            *reinterpret_cast<float4*>(&Klo[r * PADK + 8 * k0 + 4]) =
                make_float4(alo.z, clo.z, alo.w, clo.w);
        }

        // --- V fill (plain layout): 1024 float4 tasks, 4 per thread ---
#pragma unroll
        for (int p = 0; p < 4; ++p) {
            int idx = tid + p * 256;
            int r = idx >> 4;
            int c = (idx & 15) << 2;
            size_t gb = (size_t)(b * Kk + kt0 + r) * DMm + h * DHh + c;
            float4 vv = *reinterpret_cast<const float4*>(g_v + gb);
            float4 vh, vl;
            vh.x = tf32_rna(vv.x); vl.x = tf32_rna(vv.x - vh.x);
            vh.y = tf32_rna(vv.y); vl.y = tf32_rna(vv.y - vh.y);
            vh.z = tf32_rna(vv.z); vl.z = tf32_rna(vv.z - vh.z);
            vh.w = tf32_rna(vv.w); vl.w = tf32_rna(vv.w - vh.w);
            *reinterpret_cast<float4*>(&Vhi[r * PADV + c]) = vh;
            *reinterpret_cast<float4*>(&Vlo[r * PADV + c]) = vl;
        }
        if (tid < 128)
            Lk[tid] = klocs[(size_t)(b * Kk + kt0) * 2 + tid];
        __syncthreads();

        // --- S = Q . K^T (split tf32: hh + hl + lh) ---
        float cc[8][4];
#pragma unroll
        for (int n = 0; n < 8; ++n)
#pragma unroll
            for (int e = 0; e < 4; ++e) cc[n][e] = 0.f;

#pragma unroll
        for (int k0 = 0; k0 < 8; ++k0) {
            int kb = 8 * k0 + 2 * t;       // permuted pair offset
#pragma unroll
            for (int n = 0; n < 8; ++n) {
                int krow = (8 * n + g) * PADK;
                float2 bh = *reinterpret_cast<const float2*>(&Khi[krow + kb]);
                float2 bl = *reinterpret_cast<const float2*>(&Klo[krow + kb]);
                mma_tf32f(cc[n], qh[k0][0], qh[k0][1], qh[k0][2], qh[k0][3], bh.x, bh.y);
                mma_tf32f(cc[n], qh[k0][0], qh[k0][1], qh[k0][2], qh[k0][3], bl.x, bl.y);
                mma_tf32f(cc[n], ql[k0][0], ql[k0][1], ql[k0][2], ql[k0][3], bh.x, bh.y);
            }
        }

        // --- bias + mask + exp, row sums, stage P ---
#pragma unroll
        for (int n = 0; n < 8; ++n) {
            int klocal = 8 * n + 2 * t;
            float kxA = Lk[klocal * 2 + 0];
            float kyA = Lk[klocal * 2 + 1];
            float kxB = Lk[klocal * 2 + 2];
            float kyB = Lk[klocal * 2 + 3];
            bool vA = (kt0 + klocal) < kend;
            bool vB = (kt0 + klocal + 1) < kend;
            cc[n][0] = score_to_p(cc[n][0], qx0, qy0, kxA, kyA, vA, Tb, inv_step);
            cc[n][1] = score_to_p(cc[n][1], qx0, qy0, kxB, kyB, vB, Tb, inv_step);
            cc[n][2] = score_to_p(cc[n][2], qx1, qy1, kxA, kyA, vA, Tb, inv_step);
            cc[n][3] = score_to_p(cc[n][3], qx1, qy1, kxB, kyB, vB, Tb, inv_step);
            l0 += cc[n][0] + cc[n][1];
            l1 += cc[n][2] + cc[n][3];
            *reinterpret_cast<float2*>(&Pm[(16 * warp + g) * PADK + klocal]) =
                make_float2(cc[n][0], cc[n][1]);
            *reinterpret_cast<float2*>(&Pm[(16 * warp + g + 8) * PADK + klocal]) =
                make_float2(cc[n][2], cc[n][3]);
        }
        __syncwarp();

        // --- O += P . V (split tf32) ---
#pragma unroll
        for (int k0 = 0; k0 < 8; ++k0) {
            int ka = 8 * k0 + t;
            float pa0 = Pm[(16 * warp + g) * PADK + ka];
            float pa1 = Pm[(16 * warp + g + 8) * PADK + ka];
            float pa2 = Pm[(16 * warp + g) * PADK + ka + 4];
            float pa3 = Pm[(16 * warp + g + 8) * PADK + ka + 4];
            float ph0 = tf32_rna(pa0), pl0 = tf32_rna(pa0 - ph0);
            float ph1 = tf32_rna(pa1), pl1 = tf32_rna(pa1 - ph1);
            float ph2 = tf32_rna(pa2), pl2 = tf32_rna(pa2 - ph2);
            float ph3 = tf32_rna(pa3), pl3 = tf32_rna(pa3 - ph3);
#pragma unroll
            for (int n = 0; n < 8; ++n) {
                int vcol = 8 * n + g;
                float vh0 = Vhi[ka * PADV + vcol];
                float vh1 = Vhi[(ka + 4) * PADV + vcol];
                float vl0 = Vlo[ka * PADV + vcol];
                float vl1 = Vlo[(ka + 4) * PADV + vcol];
                mma_tf32f(o[n], ph0, ph1, ph2, ph3, vh0, vh1);
                mma_tf32f(o[n], ph0, ph1, ph2, ph3, vl0, vl1);
                mma_tf32f(o[n], pl0, pl1, pl2, pl3, vh0, vh1);
            }
        }
    }

    // Finalize: reduce row sums across the quad, normalize, write ctx
    l0 += __shfl_xor_sync(0xffffffffu, l0, 1);
    l0 += __shfl_xor_sync(0xffffffffu, l0, 2);
    l1 += __shfl_xor_sync(0xffffffffu, l1, 1);
    l1 += __shfl_xor_sync(0xffffffffu, l1, 2);
    const float i0 = 1.f / l0;
    const float i1 = 1.f / l1;

    float* c0p = g_ctx + (size_t)(b * Qq + row0) * DMm + h * DHh;
    float* c1p = g_ctx + (size_t)(b * Qq + row1) * DMm + h * DHh;
#pragma unroll
    for (int n = 0; n < 8; ++n) {
        int cc2 = 8 * n + 2 * t;
        *reinterpret_cast<float2*>(c0p + cc2) =
            make_float2(o[n][0] * i0, o[n][1] * i0);
        *reinterpret_cast<float2*>(c1p + cc2) =
            make_float2(o[n][2] * i1, o[n][3] * i1);
    }
}

// ---------------------------------------------------------------------------
// Launch (no static guards — deterministic, identical behavior every call)
// ---------------------------------------------------------------------------
#define ATTN_SMEM ((64 * PADK * 2 + 64 * PADV * 2 + 128 * PADK + NT + 128) * 4)

extern "C" void kernel_launch(void* const* d_in, const int* in_sizes, int n_in,
                              void* d_out, int out_size)
{
    const float* qs      = (const float*)d_in[0];
    const float* ks      = (const float*)d_in[1];
    const float* vs      = (const float*)d_in[2];
    const float* qs_locs = (const float*)d_in[3];
    const float* ks_locs = (const float*)d_in[4];
    const float* Wq      = (const float*)d_in[5];
    const float* bq      = (const float*)d_in[6];
    const float* Wk      = (const float*)d_in[7];
    const float* bk      = (const float*)d_in[8];
    const float* Wv      = (const float*)d_in[9];
    const float* bv      = (const float*)d_in[10];
    const float* Wo      = (const float*)d_in[11];
    const float* bo      = (const float*)d_in[12];
    const float* ap      = (const float*)d_in[13];
    const float* bp      = (const float*)d_in[14];
    const float* cp      = (const float*)d_in[15];
    const int*   vlen    = (const int*)d_in[16];
    float* out           = (float*)d_out;

    float *pq, *pk, *pv, *pctx;
    cudaGetSymbolAddress((void**)&pq,   g_q);
    cudaGetSymbolAddress((void**)&pk,   g_k);
    cudaGetSymbolAddress((void**)&pv,   g_v);
    cudaGetSymbolAddress((void**)&pctx, g_ctx);

    cudaFuncSetAttribute(attn_mma_kernel,
                         cudaFuncAttributeMaxDynamicSharedMemorySize,
                         ATTN_SMEM);

    build_bias_table<<<Hh, 256>>>(ap, bp, cp);

    dim3 ggrid(512 / 64, (Bb * Qq) / 64, 3);
    qkv_gemm_tc_kernel<<<ggrid, 128>>>(qs, ks, vs, Wq, bq, Wk, bk, Wv, bv,
                                       pq, pk, pv);

    dim3 agrid(Qq / 128, Hh, Bb);  // (16, 8, 2)
    attn_mma_kernel<<<agrid, 256, ATTN_SMEM>>>(qs_locs, ks_locs, vlen);

    dim3 ogrid(512 / 64, (Bb * Qq) / 64);
    out_gemm_tc_kernel<<<ogrid, 128>>>(pctx, Wo, bo, out);
}

// round 15
// speedup vs baseline: 1.9559x; 1.0894x over previous
#include <cuda_runtime.h>
#include <math_constants.h>
#include <cstddef>
#include <cstdint>

// Problem constants
#define Bb 2
#define Qq 2048
#define Kk 2048
#define DMm 512
#define Hh 8
#define Ff 5
#define DHh 64

// Bias lookup table
#define NT 2048
#define DMAXV 14.15f

// smem paddings
#define PADK 72     // K tile + P tile row stride (≡8 mod 32 -> LDS64 conflict-free)
#define PVS 136     // V pair-slice stride in floats (≡8 mod 32)

// Scratch (alloc-free rule: __device__ globals)
__device__ float g_q[Bb * Qq * DMm];
__device__ float g_k[Bb * Kk * DMm];
__device__ float g_v[Bb * Kk * DMm];
__device__ float g_ctx[Bb * Qq * DMm];
__device__ float g_btab[Hh * NT];

// ---------------------------------------------------------------------------
__device__ __forceinline__ float tf32_rna(float x) {
    uint32_t u;
    asm("cvt.rna.tf32.f32 %0, %1;" : "=r"(u) : "f"(x));
    return __uint_as_float(u);
}

__device__ __forceinline__ void mma_tf32(float* c,
    uint32_t a0, uint32_t a1, uint32_t a2, uint32_t a3,
    uint32_t b0, uint32_t b1)
{
    asm volatile(
        "mma.sync.aligned.m16n8k8.row.col.f32.tf32.tf32.f32 "
        "{%0,%1,%2,%3}, {%4,%5,%6,%7}, {%8,%9}, {%0,%1,%2,%3};"
        : "+f"(c[0]), "+f"(c[1]), "+f"(c[2]), "+f"(c[3])
        : "r"(a0), "r"(a1), "r"(a2), "r"(a3), "r"(b0), "r"(b1));
}

__device__ __forceinline__ void mma_tf32f(float* c,
    float a0, float a1, float a2, float a3, float b0, float b1)
{
    mma_tf32(c, __float_as_uint(a0), __float_as_uint(a1),
             __float_as_uint(a2), __float_as_uint(a3),
             __float_as_uint(b0), __float_as_uint(b1));
}

// ---------------------------------------------------------------------------
// Build per-head bias table
// ---------------------------------------------------------------------------
__global__ void build_bias_table(const float* __restrict__ apar,
                                 const float* __restrict__ bpar,
                                 const float* __restrict__ cpar)
{
    const int h = blockIdx.x;
    float af[Ff], bf[Ff], cf[Ff];
#pragma unroll
    for (int f = 0; f < Ff; ++f) {
        af[f] = apar[h * Ff + f];
        bf[f] = fabsf(bpar[h * Ff + f]);
        cf[f] = cpar[h * Ff + f];
    }
    const float step = DMAXV / (float)(NT - 1);
    for (int i = threadIdx.x; i < NT; i += blockDim.x) {
        float d = i * step;
        float s = 0.f;
#pragma unroll
        for (int f = 0; f < Ff; ++f) {
            float t = d - cf[f];
            s = fmaf(af[f], __expf(-bf[f] * t * t), s);
        }
        g_btab[h * NT + i] = s;
    }
}

// ---------------------------------------------------------------------------
// tf32 tensor-core GEMM with hi/lo split (validated; unchanged).
// ---------------------------------------------------------------------------
__device__ __forceinline__ void gemm512_tc_body(
    const float* __restrict__ A, const float* __restrict__ W,
    const float* __restrict__ bias, float* __restrict__ C, float scale,
    int rowBase, int colBase)
{
    __shared__ __align__(16) float Ah[64][20], Al[64][20];
    __shared__ __align__(16) float Bh[16][72], Bl[16][72];

    const int tid = threadIdx.x;
    const int lane = tid & 31;
    const int warp = tid >> 5;
    const int wm = (warp & 1) * 32;
    const int wn = (warp >> 1) * 32;
    const int g = lane >> 2;
    const int t = lane & 3;

    float acc[2][4][4];
#pragma unroll
    for (int mi = 0; mi < 2; ++mi)
#pragma unroll
        for (int ni = 0; ni < 4; ++ni)
#pragma unroll
            for (int e = 0; e < 4; ++e) acc[mi][ni][e] = 0.f;

    const int arow = tid >> 2;
    const int acol = (tid & 3) << 2;
    const int brow = tid >> 4;
    const int bcol = (tid & 15) << 2;

    for (int k0 = 0; k0 < 512; k0 += 16) {
        __syncthreads();
#pragma unroll
        for (int p = 0; p < 2; ++p) {
            float4 va = *reinterpret_cast<const float4*>(
                A + (size_t)(rowBase + arow + p * 32) * 512 + k0 + acol);
            float4 hA, lA;
            hA.x = tf32_rna(va.x); lA.x = tf32_rna(va.x - hA.x);
            hA.y = tf32_rna(va.y); lA.y = tf32_rna(va.y - hA.y);
            hA.z = tf32_rna(va.z); lA.z = tf32_rna(va.z - hA.z);
            hA.w = tf32_rna(va.w); lA.w = tf32_rna(va.w - hA.w);
            *reinterpret_cast<float4*>(&Ah[arow + p * 32][acol]) = hA;
            *reinterpret_cast<float4*>(&Al[arow + p * 32][acol]) = lA;

            float4 vb = *reinterpret_cast<const float4*>(
                W + (size_t)(k0 + brow + p * 8) * 512 + colBase + bcol);
            float4 hB, lB;
            hB.x = tf32_rna(vb.x); lB.x = tf32_rna(vb.x - hB.x);
            hB.y = tf32_rna(vb.y); lB.y = tf32_rna(vb.y - hB.y);
            hB.z = tf32_rna(vb.z); lB.z = tf32_rna(vb.z - hB.z);
            hB.w = tf32_rna(vb.w); lB.w = tf32_rna(vb.w - hB.w);
            *reinterpret_cast<float4*>(&Bh[brow + p * 8][bcol]) = hB;
            *reinterpret_cast<float4*>(&Bl[brow + p * 8][bcol]) = lB;
        }
        __syncthreads();

#pragma unroll
        for (int kk = 0; kk < 16; kk += 8) {
            uint32_t ah[2][4], al[2][4];
#pragma unroll
            for (int mi = 0; mi < 2; ++mi) {
                int r0 = wm + mi * 16 + g;
                ah[mi][0] = __float_as_uint(Ah[r0][kk + t]);
                ah[mi][1] = __float_as_uint(Ah[r0 + 8][kk + t]);
                ah[mi][2] = __float_as_uint(Ah[r0][kk + t + 4]);
                ah[mi][3] = __float_as_uint(Ah[r0 + 8][kk + t + 4]);
                al[mi][0] = __float_as_uint(Al[r0][kk + t]);
                al[mi][1] = __float_as_uint(Al[r0 + 8][kk + t]);
                al[mi][2] = __float_as_uint(Al[r0][kk + t + 4]);
                al[mi][3] = __float_as_uint(Al[r0 + 8][kk + t + 4]);
            }
            uint32_t bh[4][2], bl[4][2];
#pragma unroll
            for (int ni = 0; ni < 4; ++ni) {
                int c0 = wn + ni * 8 + g;
                bh[ni][0] = __float_as_uint(Bh[kk + t][c0]);
                bh[ni][1] = __float_as_uint(Bh[kk + t + 4][c0]);
                bl[ni][0] = __float_as_uint(Bl[kk + t][c0]);
                bl[ni][1] = __float_as_uint(Bl[kk + t + 4][c0]);
            }
#pragma unroll
            for (int mi = 0; mi < 2; ++mi)
#pragma unroll
                for (int ni = 0; ni < 4; ++ni) {
                    mma_tf32(acc[mi][ni], ah[mi][0], ah[mi][1], ah[mi][2], ah[mi][3],
                             bh[ni][0], bh[ni][1]);
                    mma_tf32(acc[mi][ni], ah[mi][0], ah[mi][1], ah[mi][2], ah[mi][3],
                             bl[ni][0], bl[ni][1]);
                    mma_tf32(acc[mi][ni], al[mi][0], al[mi][1], al[mi][2], al[mi][3],
                             bh[ni][0], bh[ni][1]);
                }
        }
    }

#pragma unroll
    for (int mi = 0; mi < 2; ++mi)
#pragma unroll
        for (int ni = 0; ni < 4; ++ni) {
            int rr = rowBase + wm + mi * 16 + g;
            int cc = colBase + wn + ni * 8 + t * 2;
            float b0 = bias[cc], b1 = bias[cc + 1];
            float2 v0 = make_float2((acc[mi][ni][0] + b0) * scale,
                                    (acc[mi][ni][1] + b1) * scale);
            float2 v1 = make_float2((acc[mi][ni][2] + b0) * scale,
                                    (acc[mi][ni][3] + b1) * scale);
            *reinterpret_cast<float2*>(C + (size_t)rr * 512 + cc) = v0;
            *reinterpret_cast<float2*>(C + (size_t)(rr + 8) * 512 + cc) = v1;
        }
}

__global__ __launch_bounds__(128) void qkv_gemm_tc_kernel(
    const float* __restrict__ qs, const float* __restrict__ ks,
    const float* __restrict__ vs,
    const float* __restrict__ Wq, const float* __restrict__ bq,
    const float* __restrict__ Wk, const float* __restrict__ bk,
    const float* __restrict__ Wv, const float* __restrict__ bv,
    float* __restrict__ oq, float* __restrict__ ok, float* __restrict__ ov)
{
    const int z = blockIdx.z;
    const float* A = (z == 0) ? qs : (z == 1) ? ks : vs;
    const float* W = (z == 0) ? Wq : (z == 1) ? Wk : Wv;
    const float* bias = (z == 0) ? bq : (z == 1) ? bk : bv;
    float* C = (z == 0) ? oq : (z == 1) ? ok : ov;
    const float scale = (z == 0) ? 0.125f : 1.0f;
    gemm512_tc_body(A, W, bias, C, scale, blockIdx.y * 64, blockIdx.x * 64);
}

__global__ __launch_bounds__(128) void out_gemm_tc_kernel(
    const float* __restrict__ A, const float* __restrict__ W,
    const float* __restrict__ bias, float* __restrict__ C)
{
    gemm512_tc_body(A, W, bias, C, 1.0f, blockIdx.y * 64, blockIdx.x * 64);
}

// ---------------------------------------------------------------------------
// Bias + exp helper for one score element
// ---------------------------------------------------------------------------
__device__ __forceinline__ float score_to_p(
    float s, float qx, float qy, float kx, float ky, bool valid,
    const float* __restrict__ Tb, float inv_step)
{
    float dx = qx - kx, dy = qy - ky;
    float d2 = fmaf(dx, dx, dy * dy);
    d2 = fmaxf(d2, 1e-20f);
    float dist = d2 * rsqrtf(d2);
    float tt = dist * inv_step;
    int i0 = min((int)tt, NT - 2);
    float frac = tt - (float)i0;
    float b0 = Tb[i0], b1 = Tb[i0 + 1];
    s += fmaf(frac, b1 - b0, b0);
    s = valid ? s : -1e30f;      // exp -> 0 for masked keys
    return __expf(s);
}

// ---------------------------------------------------------------------------
// MMA flash attention, 256 threads (8 warps x 16 q rows = 128 q rows/CTA).
// Reduced-split tf32: q exact x kh (2 mma), P exact x vh (2 mma).
// K: permuted columns (pair (t,t+4) = one LDS.64).
// V: pair-interleaved across rows ka/ka+4 (one LDS.64 per fragment).
// ---------------------------------------------------------------------------
__global__ __launch_bounds__(256) void attn_mma_kernel(
    const float* __restrict__ qlocs, const float* __restrict__ klocs,
    const int* __restrict__ valid_lens)
{
    extern __shared__ float sm[];
    float* Khi = sm;                       // 64*PADK (permuted cols, hi only)
    float* Vp  = Khi + 64 * PADK;          // 32*PVS (pair slices, hi only)
    float* Pm  = Vp  + 32 * PVS;           // 128*PADK
    float* Tb  = Pm  + 128 * PADK;         // NT
    float* Lk  = Tb  + NT;                 // 128

    const int tid = threadIdx.x;
    const int lane = tid & 31;
    const int warp = tid >> 5;             // 0..7
    const int g = lane >> 2;
    const int t = lane & 3;
    const int h = blockIdx.y;
    const int b = blockIdx.z;
    const int row0 = blockIdx.x * 128 + warp * 16 + g;
    const int row1 = row0 + 8;

    // Bias table -> smem (2048 floats, 256 threads -> 2 float4 each)
#pragma unroll
    for (int i = 0; i < 2; ++i) {
        int v = (tid + i * 256) << 2;
        *reinterpret_cast<float4*>(&Tb[v]) =
            *reinterpret_cast<const float4*>(g_btab + h * NT + v);
    }

    // Q A-fragments (hi/lo, exact), resident for the whole kernel
    float qh[8][4], ql[8][4];
    {
        const float* q0 = g_q + (size_t)(b * Qq + row0) * DMm + h * DHh;
        const float* q1 = g_q + (size_t)(b * Qq + row1) * DMm + h * DHh;
#pragma unroll
        for (int k0 = 0; k0 < 8; ++k0) {
            float v0 = q0[8 * k0 + t];
            float v1 = q1[8 * k0 + t];
            float v2 = q0[8 * k0 + t + 4];
            float v3 = q1[8 * k0 + t + 4];
            qh[k0][0] = tf32_rna(v0); ql[k0][0] = tf32_rna(v0 - qh[k0][0]);
            qh[k0][1] = tf32_rna(v1); ql[k0][1] = tf32_rna(v1 - qh[k0][1]);
            qh[k0][2] = tf32_rna(v2); ql[k0][2] = tf32_rna(v2 - qh[k0][2]);
            qh[k0][3] = tf32_rna(v3); ql[k0][3] = tf32_rna(v3 - qh[k0][3]);
        }
    }
    const float qx0 = qlocs[(size_t)(b * Qq + row0) * 2 + 0];
    const float qy0 = qlocs[(size_t)(b * Qq + row0) * 2 + 1];
    const float qx1 = qlocs[(size_t)(b * Qq + row1) * 2 + 0];
    const float qy1 = qlocs[(size_t)(b * Qq + row1) * 2 + 1];
    const float inv_step = (float)(NT - 1) / DMAXV;

    float o[8][4];
#pragma unroll
    for (int n = 0; n < 8; ++n)
#pragma unroll
        for (int e = 0; e < 4; ++e) o[n][e] = 0.f;
    float l0 = 0.f, l1 = 0.f;

    const int kend = valid_lens[b];

    for (int kt0 = 0; kt0 < kend; kt0 += 64) {
        __syncthreads();

        // --- K fill, permuted cols (pairs (p,p+4) adjacent), hi only ---
        // 512 tasks = 64 rows x 8 col-groups; 256 threads -> 2 each.
#pragma unroll
        for (int i = 0; i < 2; ++i) {
            int task = tid + i * 256;
            int r = task >> 3;
            int k0 = task & 7;
            size_t gb = (size_t)(b * Kk + kt0 + r) * DMm + h * DHh + 8 * k0;
            float4 a = *reinterpret_cast<const float4*>(g_k + gb);
            float4 c = *reinterpret_cast<const float4*>(g_k + gb + 4);
            float4 ah, ch;
            ah.x = tf32_rna(a.x); ah.y = tf32_rna(a.y);
            ah.z = tf32_rna(a.z); ah.w = tf32_rna(a.w);
            ch.x = tf32_rna(c.x); ch.y = tf32_rna(c.y);
            ch.z = tf32_rna(c.z); ch.w = tf32_rna(c.w);
            *reinterpret_cast<float4*>(&Khi[r * PADK + 8 * k0]) =
                make_float4(ah.x, ch.x, ah.y, ch.y);
            *reinterpret_cast<float4*>(&Khi[r * PADK + 8 * k0 + 4]) =
                make_float4(ah.z, ch.z, ah.w, ch.w);
        }

        // --- V fill, pair-interleaved across rows (r, r+4), hi only ---
        // 512 tasks = (k0:8) x (j:4) x (cblock:16); 2 per thread.
#pragma unroll
        for (int i = 0; i < 2; ++i) {
            int task = tid + i * 256;
            int cb = task & 15;
            int j = (task >> 4) & 3;
            int k0 = task >> 6;
            int r = 8 * k0 + j;
            int c = cb * 4;
            size_t gb = (size_t)(b * Kk + kt0 + r) * DMm + h * DHh + c;
            float4 a = *reinterpret_cast<const float4*>(g_v + gb);
            float4 d = *reinterpret_cast<const float4*>(g_v + gb + 4 * DMm);
            float4 ah, dh;
            ah.x = tf32_rna(a.x); ah.y = tf32_rna(a.y);
            ah.z = tf32_rna(a.z); ah.w = tf32_rna(a.w);
            dh.x = tf32_rna(d.x); dh.y = tf32_rna(d.y);
            dh.z = tf32_rna(d.z); dh.w = tf32_rna(d.w);
            int dst = (k0 * 4 + j) * PVS + 2 * c;
            *reinterpret_cast<float4*>(&Vp[dst]) =
                make_float4(ah.x, dh.x, ah.y, dh.y);
            *reinterpret_cast<float4*>(&Vp[dst + 4]) =
                make_float4(ah.z, dh.z, ah.w, dh.w);
        }
        if (tid < 128)
            Lk[tid] = klocs[(size_t)(b * Kk + kt0) * 2 + tid];
        __syncthreads();

        // --- S = Q . K^T : (qh + ql) x kh, 2 mmas ---
        float cc[8][4];
#pragma unroll
        for (int n = 0; n < 8; ++n)
#pragma unroll
            for (int e = 0; e < 4; ++e) cc[n][e] = 0.f;

#pragma unroll
        for (int k0 = 0; k0 < 8; ++k0) {
            int kb = 8 * k0 + 2 * t;       // permuted pair offset
#pragma unroll
            for (int n = 0; n < 8; ++n) {
                int krow = (8 * n + g) * PADK;
                float2 bh = *reinterpret_cast<const float2*>(&Khi[krow + kb]);
                mma_tf32f(cc[n], qh[k0][0], qh[k0][1], qh[k0][2], qh[k0][3], bh.x, bh.y);
                mma_tf32f(cc[n], ql[k0][0], ql[k0][1], ql[k0][2], ql[k0][3], bh.x, bh.y);
            }
        }

        // --- bias + mask + exp, row sums, stage P ---
#pragma unroll
        for (int n = 0; n < 8; ++n) {
            int klocal = 8 * n + 2 * t;
            float kxA = Lk[klocal * 2 + 0];
            float kyA = Lk[klocal * 2 + 1];
            float kxB = Lk[klocal * 2 + 2];
            float kyB = Lk[klocal * 2 + 3];
            bool vA = (kt0 + klocal) < kend;
            bool vB = (kt0 + klocal + 1) < kend;
            cc[n][0] = score_to_p(cc[n][0], qx0, qy0, kxA, kyA, vA, Tb, inv_step);
            cc[n][1] = score_to_p(cc[n][1], qx0, qy0, kxB, kyB, vB, Tb, inv_step);
            cc[n][2] = score_to_p(cc[n][2], qx1, qy1, kxA, kyA, vA, Tb, inv_step);
            cc[n][3] = score_to_p(cc[n][3], qx1, qy1, kxB, kyB, vB, Tb, inv_step);
            l0 += cc[n][0] + cc[n][1];
            l1 += cc[n][2] + cc[n][3];
            *reinterpret_cast<float2*>(&Pm[(16 * warp + g) * PADK + klocal]) =
                make_float2(cc[n][0], cc[n][1]);
            *reinterpret_cast<float2*>(&Pm[(16 * warp + g + 8) * PADK + klocal]) =
                make_float2(cc[n][2], cc[n][3]);
        }
        __syncwarp();

        // --- O += P . V : (ph + pl) x vh, 2 mmas, V frag = one LDS.64 ---
#pragma unroll
        for (int k0 = 0; k0 < 8; ++k0) {
            int ka = 8 * k0 + t;
            float pa0 = Pm[(16 * warp + g) * PADK + ka];
            float pa1 = Pm[(16 * warp + g + 8) * PADK + ka];
            float pa2 = Pm[(16 * warp + g) * PADK + ka + 4];
            float pa3 = Pm[(16 * warp + g + 8) * PADK + ka + 4];
            float ph0 = tf32_rna(pa0), pl0 = tf32_rna(pa0 - ph0);
            float ph1 = tf32_rna(pa1), pl1 = tf32_rna(pa1 - ph1);
            float ph2 = tf32_rna(pa2), pl2 = tf32_rna(pa2 - ph2);
            float ph3 = tf32_rna(pa3), pl3 = tf32_rna(pa3 - ph3);
            const float* vbase = Vp + (k0 * 4 + t) * PVS;
#pragma unroll
            for (int n = 0; n < 8; ++n) {
                float2 vv = *reinterpret_cast<const float2*>(vbase + 2 * (8 * n + g));
                mma_tf32f(o[n], ph0, ph1, ph2, ph3, vv.x, vv.y);
                mma_tf32f(o[n], pl0, pl1, pl2, pl3, vv.x, vv.y);
            }
        }
    }

    // Finalize: reduce row sums across the quad, normalize, write ctx
    l0 += __shfl_xor_sync(0xffffffffu, l0, 1);
    l0 += __shfl_xor_sync(0xffffffffu, l0, 2);
    l1 += __shfl_xor_sync(0xffffffffu, l1, 1);
    l1 += __shfl_xor_sync(0xffffffffu, l1, 2);
    const float i0 = 1.f / l0;
    const float i1 = 1.f / l1;

    float* c0p = g_ctx + (size_t)(b * Qq + row0) * DMm + h * DHh;
    float* c1p = g_ctx + (size_t)(b * Qq + row1) * DMm + h * DHh;
#pragma unroll
    for (int n = 0; n < 8; ++n) {
        int cc2 = 8 * n + 2 * t;
        *reinterpret_cast<float2*>(c0p + cc2) =
            make_float2(o[n][0] * i0, o[n][1] * i0);
        *reinterpret_cast<float2*>(c1p + cc2) =
            make_float2(o[n][2] * i1, o[n][3] * i1);
    }
}

// ---------------------------------------------------------------------------
// Launch
// ---------------------------------------------------------------------------
#define ATTN_SMEM ((64 * PADK + 32 * PVS + 128 * PADK + NT + 128) * 4)

extern "C" void kernel_launch(void* const* d_in, const int* in_sizes, int n_in,
                              void* d_out, int out_size)
{
    const float* qs      = (const float*)d_in[0];
    const float* ks      = (const float*)d_in[1];
    const float* vs      = (const float*)d_in[2];
    const float* qs_locs = (const float*)d_in[3];
    const float* ks_locs = (const float*)d_in[4];
    const float* Wq      = (const float*)d_in[5];
    const float* bq      = (const float*)d_in[6];
    const float* Wk      = (const float*)d_in[7];
    const float* bk      = (const float*)d_in[8];
    const float* Wv      = (const float*)d_in[9];
    const float* bv      = (const float*)d_in[10];
    const float* Wo      = (const float*)d_in[11];
    const float* bo      = (const float*)d_in[12];
    const float* ap      = (const float*)d_in[13];
    const float* bp      = (const float*)d_in[14];
    const float* cp      = (const float*)d_in[15];
    const int*   vlen    = (const int*)d_in[16];
    float* out           = (float*)d_out;

    float *pq, *pk, *pv, *pctx;
    cudaGetSymbolAddress((void**)&pq,   g_q);
    cudaGetSymbolAddress((void**)&pk,   g_k);
    cudaGetSymbolAddress((void**)&pv,   g_v);
    cudaGetSymbolAddress((void**)&pctx, g_ctx);

    cudaFuncSetAttribute(attn_mma_kernel,
                         cudaFuncAttributeMaxDynamicSharedMemorySize,
                         ATTN_SMEM);

    build_bias_table<<<Hh, 256>>>(ap, bp, cp);

    dim3 ggrid(512 / 64, (Bb * Qq) / 64, 3);
    qkv_gemm_tc_kernel<<<ggrid, 128>>>(qs, ks, vs, Wq, bq, Wk, bk, Wv, bv,
                                       pq, pk, pv);

    dim3 agrid(Qq / 128, Hh, Bb);  // (16, 8, 2)
    attn_mma_kernel<<<agrid, 256, ATTN_SMEM>>>(qs_locs, ks_locs, vlen);

    dim3 ogrid(512 / 64, (Bb * Qq) / 64);
    out_gemm_tc_kernel<<<ogrid, 128>>>(pctx, Wo, bo, out);
}